// round 12
// baseline (speedup 1.0000x reference)
#include <cuda_runtime.h>
#include <cuda_bf16.h>

#define NN 50000
#define DD 64
#define EE 800000
#define CAP 2048
#define NEG_INF (-3.402823466e38f)

// ---------------- scratch (static device globals; no allocation) ----------------
__device__ __align__(16) float g_score[NN];
__device__ __align__(16) float g_deg[NN];
__device__ __align__(16) int   g_cnt[NN];
__device__ __align__(16) int   g_off[NN];
__device__ __align__(16) int   g_cur[NN];
__device__ __align__(16) int   g_src[EE];
__device__ __align__(16) float g_wv[EE];
__device__ __align__(16) unsigned int g_hist[4096];
__device__ __align__(16) float g_W[64 * 64];
__device__ __align__(16) float g_xw[(size_t)NN * 64];

__device__ __forceinline__ unsigned int key_of(float f) {
    unsigned int u = __float_as_uint(f);
    return u ^ ((u >> 31) ? 0xFFFFFFFFu : 0x80000000u);   // monotone: float order -> uint order
}

// ---------------- 1) zero cnt/cur/deg/hist ----------------
__global__ void zero_kernel() {
    int i = blockIdx.x * blockDim.x + threadIdx.x;
    if (i < NN) { g_cnt[i] = 0; g_cur[i] = 0; g_deg[i] = 1.0f; }   // deg init: self-loop
    if (i < 4096) g_hist[i] = 0u;
}

// ---------------- 2) fused: score (+hist) blocks | edge count blocks ----------------
#define SCORE_BLOCKS 6250
__global__ void score_count_kernel(const float* __restrict__ x, const float* __restrict__ p,
                                   const int* __restrict__ ei, const float* __restrict__ ew) {
    if (blockIdx.x < SCORE_BLOCKS) {
        int warp = (blockIdx.x * 256 + threadIdx.x) >> 5;
        int lane = threadIdx.x & 31;
        if (warp >= NN) return;
        float s = x[warp * 64 + lane] * p[lane] + x[warp * 64 + lane + 32] * p[lane + 32];
        #pragma unroll
        for (int off = 16; off > 0; off >>= 1) s += __shfl_down_sync(0xffffffffu, s, off);
        if (lane == 0) {
            g_score[warp] = s;
            atomicAdd(&g_hist[key_of(s) >> 20], 1u);  // 4096 bins
        }
    } else {
        int e = (blockIdx.x - SCORE_BLOCKS) * 256 + threadIdx.x;
        if (e < EE) {
            int c = ei[EE + e];
            atomicAdd(&g_deg[c], ew[e]);
            atomicAdd(&g_cnt[c], 1);
        }
    }
}

// ---------------- 3) fused: block 0 = thresh + collect + top64 + GRU; block 1 = CSR scan ----------------
__global__ __launch_bounds__(1024) void topk_gru_scan_kernel(
        const float* __restrict__ x, const float* __restrict__ p,
        const float* __restrict__ h0,
        const float* __restrict__ Wih, const float* __restrict__ Whh,
        const float* __restrict__ bih, const float* __restrict__ bhh) {
    __shared__ __align__(16) char s_buf[2 * 64 * 65 * 4];  // 33.3 KB, phase-reused
    __shared__ int   s_scanA[1024];
    __shared__ float s_vals[64];
    __shared__ int   s_perm[64];
    __shared__ float s_st[64];
    __shared__ unsigned int s_thresh;
    __shared__ int   s_cnt;
    __shared__ float s_rpn;
    __shared__ int   s_wtot[32];
    __shared__ int   s_carry;

    int tid = threadIdx.x;
    int lane = tid & 31;
    int wid = tid >> 5;

    if (blockIdx.x == 0) {
        // ---- phase A1: threshold bin (each thread owns 4 bins, top-down) ----
        int s = 0;
        #pragma unroll
        for (int i = 0; i < 4; i++) s += (int)g_hist[4095 - 4 * tid - i];
        int chunk = s;
        s_scanA[tid] = s;
        __syncthreads();
        int v = s;
        for (int off = 1; off < 1024; off <<= 1) {
            int add = (tid >= off) ? s_scanA[tid - off] : 0;
            __syncthreads();
            v += add; s_scanA[tid] = v;
            __syncthreads();
        }
        int excl = v - chunk;
        if (excl < 64 && v >= 64) {
            int acc = excl;
            #pragma unroll
            for (int i = 0; i < 4; i++) {
                int b = 4095 - 4 * tid - i;
                acc += (int)g_hist[b];
                if (acc >= 64) { s_thresh = ((unsigned int)b) << 20; break; }
            }
        }
        if (tid == 0) s_cnt = 0;
        __syncthreads();

        // ---- phase A2: collect candidates into smem ----
        float* sv = (float*)s_buf;
        int*   si = (int*)(s_buf + CAP * 4);
        unsigned int th = s_thresh;
        for (int n = tid; n < NN; n += 1024) {
            float sc = g_score[n];
            if (key_of(sc) >= th) {
                int pos = atomicAdd(&s_cnt, 1);
                if (pos < CAP) { sv[pos] = sc; si[pos] = n; }
            }
        }
        __syncthreads();

        // ---- phase A3: exact top-64, warp 0 only ----
        if (wid == 0) {
            int M = s_cnt; if (M > CAP) M = CAP;
            for (int k = 0; k < 64; k++) {
                float bv = NEG_INF; int bg = 0x7fffffff, bs = 0;
                for (int t = lane; t < M; t += 32) {
                    float vv = sv[t]; int g = si[t];
                    if (vv > bv || (vv == bv && g < bg)) { bv = vv; bg = g; bs = t; }
                }
                #pragma unroll
                for (int off = 16; off > 0; off >>= 1) {
                    float ov = __shfl_down_sync(0xffffffffu, bv, off);
                    int   og = __shfl_down_sync(0xffffffffu, bg, off);
                    int   os = __shfl_down_sync(0xffffffffu, bs, off);
                    if (ov > bv || (ov == bv && og < bg)) { bv = ov; bg = og; bs = os; }
                }
                bv = __shfl_sync(0xffffffffu, bv, 0);
                bg = __shfl_sync(0xffffffffu, bg, 0);
                bs = __shfl_sync(0xffffffffu, bs, 0);
                if (lane == 0) { s_vals[k] = bv; s_perm[k] = bg; sv[bs] = NEG_INF; }
                __syncwarp();
            }
            // ||p||
            float pv0 = p[lane], pv1 = p[lane + 32];
            float sq = pv0 * pv0 + pv1 * pv1;
            #pragma unroll
            for (int off = 16; off > 0; off >>= 1) sq += __shfl_down_sync(0xffffffffu, sq, off);
            if (lane == 0) s_rpn = rsqrtf(sq);
        }
        __syncthreads();
        if (tid < 64) s_st[tid] = tanhf(s_vals[tid] * s_rpn);
        __syncthreads();

        // ---- phase B: GRU (reuse s_buf as sxt/sh0, stride-65 padded) ----
        float* sxt = (float*)s_buf;
        float* sh0 = sxt + 64 * 65;
        for (int idx = tid; idx < 4096; idx += 1024) {
            int i = idx >> 6, k = idx & 63;
            sxt[i * 65 + k] = x[(size_t)s_perm[i] * 64 + k] * s_st[i];
            sh0[i * 65 + k] = h0[idx];
        }
        __syncthreads();

        int j = tid >> 4;          // 0..63 (2 distinct j per warp -> near-broadcast weight loads)
        int isub = tid & 15;       // 4 rows per thread: isub + 16*m
        float b_ir = bih[j], b_iz = bih[64 + j], b_in = bih[128 + j];
        float b_hr = bhh[j], b_hz = bhh[64 + j], b_hn = bhh[128 + j];
        float gir[4], giz[4], gin[4], ghr[4], ghz[4], ghn[4];
        #pragma unroll
        for (int m = 0; m < 4; m++) { gir[m] = b_ir; giz[m] = b_iz; gin[m] = b_in;
                                      ghr[m] = b_hr; ghz[m] = b_hz; ghn[m] = b_hn; }
        const float* wrp = Wih + j * 64;
        const float* wzp = Wih + (64 + j) * 64;
        const float* wnp = Wih + (128 + j) * 64;
        const float* vrp = Whh + j * 64;
        const float* vzp = Whh + (64 + j) * 64;
        const float* vnp = Whh + (128 + j) * 64;
        #pragma unroll 4
        for (int k = 0; k < 64; k++) {
            float wr = wrp[k], wz = wzp[k], wn = wnp[k];
            float vr = vrp[k], vz = vzp[k], vn = vnp[k];
            #pragma unroll
            for (int m = 0; m < 4; m++) {
                int i = isub + 16 * m;
                float xt = sxt[i * 65 + k], hh = sh0[i * 65 + k];
                gir[m] += xt * wr; giz[m] += xt * wz; gin[m] += xt * wn;
                ghr[m] += hh * vr; ghz[m] += hh * vz; ghn[m] += hh * vn;
            }
        }
        #pragma unroll
        for (int m = 0; m < 4; m++) {
            int i = isub + 16 * m;
            float r   = 1.f / (1.f + expf(-(gir[m] + ghr[m])));
            float z   = 1.f / (1.f + expf(-(giz[m] + ghz[m])));
            float nnv = tanhf(gin[m] + r * ghn[m]);
            g_W[i * 64 + j] = (1.f - z) * nnv + z * sh0[i * 65 + j];
        }
    } else {
        // ---- block 1: exclusive scan of g_cnt -> g_off (tiled warp-scan, int4) ----
        if (tid == 0) s_carry = 0;
        __syncthreads();
        for (int tile = 0; tile < 13; tile++) {
            int base = tile * 4096 + tid * 4;
            int a0 = 0, a1 = 0, a2 = 0, a3 = 0;
            if (base + 3 < NN) {
                int4 v4 = *(const int4*)&g_cnt[base];
                a0 = v4.x; a1 = v4.y; a2 = v4.z; a3 = v4.w;
            } else if (base < NN) {
                a0 = g_cnt[base];
                if (base + 1 < NN) a1 = g_cnt[base + 1];
                if (base + 2 < NN) a2 = g_cnt[base + 2];
            }
            int local = a0 + a1 + a2 + a3;
            int incl = local;
            #pragma unroll
            for (int off = 1; off < 32; off <<= 1) {
                int nvb = __shfl_up_sync(0xffffffffu, incl, off);
                if (lane >= off) incl += nvb;
            }
            if (lane == 31) s_wtot[wid] = incl;
            __syncthreads();
            if (wid == 0) {
                int wv = s_wtot[lane];
                int wincl = wv;
                #pragma unroll
                for (int off = 1; off < 32; off <<= 1) {
                    int nvb = __shfl_up_sync(0xffffffffu, wincl, off);
                    if (lane >= off) wincl += nvb;
                }
                s_wtot[lane] = wincl - wv;   // exclusive warp offsets
            }
            __syncthreads();
            int texcl = s_carry + s_wtot[wid] + (incl - local);
            if (base + 3 < NN) {
                int4 o; o.x = texcl; o.y = texcl + a0; o.z = texcl + a0 + a1; o.w = texcl + a0 + a1 + a2;
                *(int4*)&g_off[base] = o;
            } else if (base < NN) {
                g_off[base] = texcl;
                if (base + 1 < NN) g_off[base + 1] = texcl + a0;
                if (base + 2 < NN) g_off[base + 2] = texcl + a0 + a1;
            }
            __syncthreads();
            if (tid == 1023) s_carry = texcl + local;
            __syncthreads();
        }
    }
}

// ---------------- 4) fused: fill CSR blocks | xw = x@W blocks ----------------
#define FILL_BLOCKS 3125
__global__ void fill_xw_kernel(const int* __restrict__ ei, const float* __restrict__ ew,
                               const float* __restrict__ x) {
    if (blockIdx.x < FILL_BLOCKS) {
        int e = blockIdx.x * 256 + threadIdx.x;
        if (e >= EE) return;
        int r = ei[e];
        int c = ei[EE + e];
        float nrm = rsqrtf(g_deg[r]) * ew[e] * rsqrtf(g_deg[c]);
        int pos = g_off[c] + atomicAdd(&g_cur[c], 1);
        g_src[pos] = r;
        g_wv[pos] = nrm;
    } else {
        __shared__ float sW[64][64];
        __shared__ float sx[16][64];
        int tid = threadIdx.x;
        for (int i = tid; i < 1024; i += 256) ((float4*)sW)[i] = ((const float4*)g_W)[i];
        int row0 = (blockIdx.x - FILL_BLOCKS) * 16;
        ((float4*)sx)[tid] = ((const float4*)(x + (size_t)row0 * 64))[tid];
        __syncthreads();
        int r = tid >> 4, c4 = tid & 15;
        float4 acc = make_float4(0.f, 0.f, 0.f, 0.f);
        #pragma unroll 16
        for (int k = 0; k < 64; k++) {
            float xv = sx[r][k];
            float4 w4 = *(const float4*)&sW[k][c4 * 4];
            acc.x += xv * w4.x; acc.y += xv * w4.y; acc.z += xv * w4.z; acc.w += xv * w4.w;
        }
        ((float4*)g_xw)[(size_t)(row0 + r) * 16 + c4] = acc;
    }
}

// ---------------- 5) gather + self-loop + relu + Linear(D,1), fully fused ----------------
__global__ void gather_out_kernel(const float* __restrict__ linW, const float* __restrict__ linb,
                                  float* __restrict__ out) {
    int warp = (blockIdx.x * blockDim.x + threadIdx.x) >> 5;
    int lane = threadIdx.x & 31;
    if (warp >= NN) return;
    int start = g_off[warp];
    int end   = start + g_cnt[warp];
    float2 acc = make_float2(0.f, 0.f);
    int e = start;
    for (; e + 1 < end; e += 2) {
        int   s0 = g_src[e],     s1 = g_src[e + 1];
        float w0 = g_wv[e],      w1 = g_wv[e + 1];
        float2 v0 = ((const float2*)g_xw)[s0 * 32 + lane];
        float2 v1 = ((const float2*)g_xw)[s1 * 32 + lane];
        acc.x += w0 * v0.x + w1 * v1.x;
        acc.y += w0 * v0.y + w1 * v1.y;
    }
    if (e < end) {
        int   s0 = g_src[e];
        float w0 = g_wv[e];
        float2 v0 = ((const float2*)g_xw)[s0 * 32 + lane];
        acc.x += w0 * v0.x;
        acc.y += w0 * v0.y;
    }
    float inv = 1.0f / g_deg[warp];       // self-loop norm = dinv*1*dinv
    float2 vs = ((const float2*)g_xw)[warp * 32 + lane];
    acc.x = fmaxf(acc.x + vs.x * inv, 0.f);
    acc.y = fmaxf(acc.y + vs.y * inv, 0.f);
    float2 lw = ((const float2*)linW)[lane];
    float dot = acc.x * lw.x + acc.y * lw.y;
    #pragma unroll
    for (int off = 16; off > 0; off >>= 1) dot += __shfl_down_sync(0xffffffffu, dot, off);
    if (lane == 0) out[warp] = dot + linb[0];
}

// ---------------- launch ----------------
extern "C" void kernel_launch(void* const* d_in, const int* in_sizes, int n_in,
                              void* d_out, int out_size) {
    const float* x      = (const float*)d_in[0];
    const int*   ei     = (const int*)d_in[1];     // int32 (JAX x64 disabled)
    const float* ew     = (const float*)d_in[2];
    const float* pool_p = (const float*)d_in[3];
    const float* init_W = (const float*)d_in[4];
    const float* Wih    = (const float*)d_in[5];
    const float* Whh    = (const float*)d_in[6];
    const float* bih    = (const float*)d_in[7];
    const float* bhh    = (const float*)d_in[8];
    const float* linW   = (const float*)d_in[9];
    const float* linb   = (const float*)d_in[10];
    float* out = (float*)d_out;

    zero_kernel<<<(NN + 255) / 256, 256>>>();
    score_count_kernel<<<SCORE_BLOCKS + (EE + 255) / 256, 256>>>(x, pool_p, ei, ew);
    topk_gru_scan_kernel<<<2, 1024>>>(x, pool_p, init_W, Wih, Whh, bih, bhh);
    fill_xw_kernel<<<FILL_BLOCKS + (NN + 15) / 16, 256>>>(ei, ew, x);
    gather_out_kernel<<<(NN + 7) / 8, 256>>>(linW, linb, out);
}

// round 13
// speedup vs baseline: 1.1386x; 1.1386x over previous
#include <cuda_runtime.h>
#include <cuda_bf16.h>

#define NN 50000
#define DD 64
#define EE 800000
#define CAP 4096
#define NEG_INF (-3.402823466e38f)

// ---------------- scratch (static device globals; no allocation) ----------------
__device__ __align__(16) float g_score[NN];
__device__ __align__(16) float g_deg[NN];
__device__ __align__(16) int   g_cnt[NN];
__device__ __align__(16) int   g_off[NN];     // after fill: end offset (start+cnt)
__device__ __align__(16) long long g_edge[EE];  // packed (norm<<32 | src)
__device__ __align__(16) unsigned int g_hist[4096];
__device__ unsigned int g_thresh_key;
__device__ int g_ccount;
__device__ __align__(16) float g_cand_val[CAP];
__device__ __align__(16) int   g_cand_idx[CAP];
__device__ __align__(16) int   g_perm[64];
__device__ __align__(16) float g_vals[64];
__device__ __align__(16) float g_W[64 * 64];
__device__ __align__(16) float g_xw[(size_t)NN * 64];

__device__ __forceinline__ unsigned int key_of(float f) {
    unsigned int u = __float_as_uint(f);
    return u ^ ((u >> 31) ? 0xFFFFFFFFu : 0x80000000u);   // monotone: float order -> uint order
}

// ---------------- 1) zero cnt/deg/hist/counter ----------------
__global__ void zero_kernel() {
    int i = blockIdx.x * blockDim.x + threadIdx.x;
    if (i < NN) { g_cnt[i] = 0; g_deg[i] = 1.0f; }   // deg init: self-loop weight
    if (i < 4096) g_hist[i] = 0u;
    if (i == 0) g_ccount = 0;
}

// ---------------- 2) fused wide: score (+hist) blocks | edge deg/count blocks ----------------
#define SCORE_BLOCKS 6250
__global__ void score_count_kernel(const float* __restrict__ x, const float* __restrict__ p,
                                   const int* __restrict__ ei, const float* __restrict__ ew) {
    if (blockIdx.x < SCORE_BLOCKS) {
        int warp = (blockIdx.x * 256 + threadIdx.x) >> 5;
        int lane = threadIdx.x & 31;
        if (warp >= NN) return;
        float s = x[warp * 64 + lane] * p[lane] + x[warp * 64 + lane + 32] * p[lane + 32];
        #pragma unroll
        for (int off = 16; off > 0; off >>= 1) s += __shfl_down_sync(0xffffffffu, s, off);
        if (lane == 0) {
            g_score[warp] = s;
            atomicAdd(&g_hist[key_of(s) >> 20], 1u);  // 4096 bins
        }
    } else {
        int e = (blockIdx.x - SCORE_BLOCKS) * 256 + threadIdx.x;
        if (e < EE) {
            int c = ei[EE + e];
            atomicAdd(&g_deg[c], ew[e]);
            atomicAdd(&g_cnt[c], 1);
        }
    }
}

// ---------------- 3) single-block exclusive scan of g_cnt -> g_off (tiled warp-scan) ----------------
__global__ __launch_bounds__(1024) void scan_kernel() {
    __shared__ int s_wtot[32];
    __shared__ int s_carry;
    int tid = threadIdx.x;
    int lane = tid & 31;
    int wid = tid >> 5;
    if (tid == 0) s_carry = 0;
    __syncthreads();
    for (int tile = 0; tile < 13; tile++) {
        int base = tile * 4096 + tid * 4;
        int a0 = 0, a1 = 0, a2 = 0, a3 = 0;
        if (base + 3 < NN) {
            int4 v4 = *(const int4*)&g_cnt[base];
            a0 = v4.x; a1 = v4.y; a2 = v4.z; a3 = v4.w;
        } else if (base < NN) {
            a0 = g_cnt[base];
            if (base + 1 < NN) a1 = g_cnt[base + 1];
            if (base + 2 < NN) a2 = g_cnt[base + 2];
        }
        int local = a0 + a1 + a2 + a3;
        int incl = local;
        #pragma unroll
        for (int off = 1; off < 32; off <<= 1) {
            int nv = __shfl_up_sync(0xffffffffu, incl, off);
            if (lane >= off) incl += nv;
        }
        if (lane == 31) s_wtot[wid] = incl;
        __syncthreads();
        if (wid == 0) {
            int wv = s_wtot[lane];
            int wincl = wv;
            #pragma unroll
            for (int off = 1; off < 32; off <<= 1) {
                int nv = __shfl_up_sync(0xffffffffu, wincl, off);
                if (lane >= off) wincl += nv;
            }
            s_wtot[lane] = wincl - wv;   // exclusive warp offsets
        }
        __syncthreads();
        int texcl = s_carry + s_wtot[wid] + (incl - local);
        if (base + 3 < NN) {
            int4 o; o.x = texcl; o.y = texcl + a0; o.z = texcl + a0 + a1; o.w = texcl + a0 + a1 + a2;
            *(int4*)&g_off[base] = o;
        } else if (base < NN) {
            g_off[base] = texcl;
            if (base + 1 < NN) g_off[base + 1] = texcl + a0;
            if (base + 2 < NN) g_off[base + 2] = texcl + a0 + a1;
        }
        __syncthreads();
        if (tid == 1023) s_carry = texcl + local;
        __syncthreads();
    }
}

// ---------------- 4) find threshold bin: 64th-largest key's bin lower bound ----------------
__global__ void thresh_kernel() {
    __shared__ int chunk[256];
    __shared__ int incl[256];
    int t = threadIdx.x;
    int s = 0;
    #pragma unroll
    for (int i = 0; i < 16; i++) s += (int)g_hist[4095 - 16 * t - i];
    chunk[t] = s;
    __syncthreads();
    int v = s;
    for (int off = 1; off < 256; off <<= 1) {
        incl[t] = v; __syncthreads();
        if (t >= off) v += incl[t - off];
        __syncthreads();
    }
    incl[t] = v; __syncthreads();
    int excl = v - chunk[t];
    if (excl < 64 && v >= 64) {          // crossing chunk: walk its 16 bins from top
        int acc = excl;
        for (int i = 0; i < 16; i++) {
            int b = 4095 - 16 * t - i;
            acc += (int)g_hist[b];
            if (acc >= 64) { g_thresh_key = ((unsigned int)b) << 20; break; }
        }
    }
}

// ---------------- 5) compact candidates with key >= threshold ----------------
__global__ void collect_kernel() {
    int n = blockIdx.x * blockDim.x + threadIdx.x;
    if (n >= NN) return;
    float s = g_score[n];
    if (key_of(s) >= g_thresh_key) {
        int pos = atomicAdd(&g_ccount, 1);
        if (pos < CAP) { g_cand_val[pos] = s; g_cand_idx[pos] = n; }
    }
}

// ---------------- 6) exact top-64 over ~100 candidates (single warp) ----------------
__global__ void final_topk_kernel() {
    __shared__ float sv[CAP];
    __shared__ int   si[CAP];
    int lane = threadIdx.x;
    int M = g_ccount; if (M > CAP) M = CAP;
    for (int t = lane; t < M; t += 32) { sv[t] = g_cand_val[t]; si[t] = g_cand_idx[t]; }
    __syncwarp();
    for (int k = 0; k < 64; k++) {
        float bv = NEG_INF; int bg = 0x7fffffff, bs = 0;
        for (int t = lane; t < M; t += 32) {
            float v = sv[t]; int g = si[t];
            if (v > bv || (v == bv && g < bg)) { bv = v; bg = g; bs = t; }
        }
        #pragma unroll
        for (int off = 16; off > 0; off >>= 1) {
            float ov = __shfl_down_sync(0xffffffffu, bv, off);
            int   og = __shfl_down_sync(0xffffffffu, bg, off);
            int   os = __shfl_down_sync(0xffffffffu, bs, off);
            if (ov > bv || (ov == bv && og < bg)) { bv = ov; bg = og; bs = os; }
        }
        if (lane == 0) {
            g_vals[k] = bv;
            g_perm[k] = bg;
            sv[bs] = NEG_INF;
        }
        __syncwarp();
    }
}

// ---------------- 7) GRU step -> evolved weight W [64x64] (64 blocks x 64 threads) ----------------
__global__ void gru_kernel(const float* __restrict__ x, const float* __restrict__ p,
                           const float* __restrict__ h0,
                           const float* __restrict__ Wih, const float* __restrict__ Whh,
                           const float* __restrict__ bih, const float* __restrict__ bhh) {
    __shared__ float sxt[64][65];
    __shared__ float sh0[64][65];
    __shared__ float wr[64], wz[64], wn[64], vr[64], vz[64], vn[64];
    __shared__ float st[64];
    __shared__ float s_part[2];
    __shared__ float s_rpn;
    int t = threadIdx.x;            // 0..63
    int j = blockIdx.x;             // 0..63

    float pv = p[t];
    float sq = pv * pv;
    #pragma unroll
    for (int off = 16; off > 0; off >>= 1) sq += __shfl_down_sync(0xffffffffu, sq, off);
    if ((t & 31) == 0) s_part[t >> 5] = sq;
    __syncthreads();
    if (t == 0) s_rpn = rsqrtf(s_part[0] + s_part[1]);
    __syncthreads();
    st[t] = tanhf(g_vals[t] * s_rpn);

    wr[t] = Wih[j * 64 + t];
    wz[t] = Wih[(64 + j) * 64 + t];
    wn[t] = Wih[(128 + j) * 64 + t];
    vr[t] = Whh[j * 64 + t];
    vz[t] = Whh[(64 + j) * 64 + t];
    vn[t] = Whh[(128 + j) * 64 + t];
    __syncthreads();

    for (int i = 0; i < 64; i++) {
        sxt[i][t] = x[(size_t)g_perm[i] * 64 + t] * st[i];
        sh0[i][t] = h0[i * 64 + t];
    }
    __syncthreads();

    int i = t;
    float gir = bih[j], giz = bih[64 + j], gin = bih[128 + j];
    float ghr = bhh[j], ghz = bhh[64 + j], ghn = bhh[128 + j];
    #pragma unroll 8
    for (int k = 0; k < 64; k++) {
        float xt = sxt[i][k], hh = sh0[i][k];
        gir += xt * wr[k]; giz += xt * wz[k]; gin += xt * wn[k];
        ghr += hh * vr[k]; ghz += hh * vz[k]; ghn += hh * vn[k];
    }
    float r   = 1.f / (1.f + expf(-(gir + ghr)));
    float z   = 1.f / (1.f + expf(-(giz + ghz)));
    float nnv = tanhf(gin + r * ghn);
    g_W[i * 64 + j] = (1.f - z) * nnv + z * sh0[i][j];
}

// ---------------- 8) fill CSR: pack (src, norm) 8B into target's segment
//   slot via atomicAdd on g_off (afterwards g_off[n] = segment END) ----------------
__global__ void fill_kernel(const int* __restrict__ ei, const float* __restrict__ ew) {
    int e = blockIdx.x * blockDim.x + threadIdx.x;
    if (e >= EE) return;
    int r = ei[e];
    int c = ei[EE + e];
    float nrm = rsqrtf(g_deg[r]) * ew[e] * rsqrtf(g_deg[c]);
    int pos = atomicAdd(&g_off[c], 1);
    g_edge[pos] = ((long long)__float_as_int(nrm) << 32) | (unsigned int)r;
}

// ---------------- 9) xw = x @ W  (16 rows/block, 4 outputs/thread, float4) ----------------
__global__ void xw_kernel(const float* __restrict__ x) {
    __shared__ float sW[64][64];
    __shared__ float sx[16][64];
    int tid = threadIdx.x;
    for (int i = tid; i < 1024; i += 256) ((float4*)sW)[i] = ((const float4*)g_W)[i];
    int row0 = blockIdx.x * 16;
    ((float4*)sx)[tid] = ((const float4*)(x + (size_t)row0 * 64))[tid];
    __syncthreads();
    int r = tid >> 4, c4 = tid & 15;
    float4 acc = make_float4(0.f, 0.f, 0.f, 0.f);
    #pragma unroll 16
    for (int k = 0; k < 64; k++) {
        float xv = sx[r][k];
        float4 w4 = *(const float4*)&sW[k][c4 * 4];
        acc.x += xv * w4.x; acc.y += xv * w4.y; acc.z += xv * w4.z; acc.w += xv * w4.w;
    }
    ((float4*)g_xw)[(size_t)(row0 + r) * 16 + c4] = acc;
}

// ---------------- 10) gather + self-loop + relu + Linear(D,1), fused; unroll x4 for MLP ----------------
__global__ void gather_out_kernel(const float* __restrict__ linW, const float* __restrict__ linb,
                                  float* __restrict__ out) {
    int warp = (blockIdx.x * blockDim.x + threadIdx.x) >> 5;
    int lane = threadIdx.x & 31;
    if (warp >= NN) return;
    int end   = g_off[warp];              // post-fill: end of segment
    int start = end - g_cnt[warp];
    float2 acc = make_float2(0.f, 0.f);
    int e = start;
    for (; e + 4 <= end; e += 4) {
        long long p0 = g_edge[e],     p1 = g_edge[e + 1];
        long long p2 = g_edge[e + 2], p3 = g_edge[e + 3];
        int   s0 = (int)(p0 & 0xffffffffLL), s1 = (int)(p1 & 0xffffffffLL);
        int   s2 = (int)(p2 & 0xffffffffLL), s3 = (int)(p3 & 0xffffffffLL);
        float w0 = __int_as_float((int)(p0 >> 32)), w1 = __int_as_float((int)(p1 >> 32));
        float w2 = __int_as_float((int)(p2 >> 32)), w3 = __int_as_float((int)(p3 >> 32));
        float2 v0 = ((const float2*)g_xw)[s0 * 32 + lane];
        float2 v1 = ((const float2*)g_xw)[s1 * 32 + lane];
        float2 v2 = ((const float2*)g_xw)[s2 * 32 + lane];
        float2 v3 = ((const float2*)g_xw)[s3 * 32 + lane];
        acc.x += w0 * v0.x + w1 * v1.x + w2 * v2.x + w3 * v3.x;
        acc.y += w0 * v0.y + w1 * v1.y + w2 * v2.y + w3 * v3.y;
    }
    for (; e < end; e++) {
        long long p0 = g_edge[e];
        int   s0 = (int)(p0 & 0xffffffffLL);
        float w0 = __int_as_float((int)(p0 >> 32));
        float2 v0 = ((const float2*)g_xw)[s0 * 32 + lane];
        acc.x += w0 * v0.x;
        acc.y += w0 * v0.y;
    }
    float inv = 1.0f / g_deg[warp];       // self-loop norm = dinv*1*dinv
    float2 vs = ((const float2*)g_xw)[warp * 32 + lane];
    acc.x = fmaxf(acc.x + vs.x * inv, 0.f);
    acc.y = fmaxf(acc.y + vs.y * inv, 0.f);
    float2 lw = ((const float2*)linW)[lane];
    float dot = acc.x * lw.x + acc.y * lw.y;
    #pragma unroll
    for (int off = 16; off > 0; off >>= 1) dot += __shfl_down_sync(0xffffffffu, dot, off);
    if (lane == 0) out[warp] = dot + linb[0];
}

// ---------------- launch ----------------
extern "C" void kernel_launch(void* const* d_in, const int* in_sizes, int n_in,
                              void* d_out, int out_size) {
    const float* x      = (const float*)d_in[0];
    const int*   ei     = (const int*)d_in[1];     // int32 (JAX x64 disabled)
    const float* ew     = (const float*)d_in[2];
    const float* pool_p = (const float*)d_in[3];
    const float* init_W = (const float*)d_in[4];
    const float* Wih    = (const float*)d_in[5];
    const float* Whh    = (const float*)d_in[6];
    const float* bih    = (const float*)d_in[7];
    const float* bhh    = (const float*)d_in[8];
    const float* linW   = (const float*)d_in[9];
    const float* linb   = (const float*)d_in[10];
    float* out = (float*)d_out;

    zero_kernel<<<(NN + 255) / 256, 256>>>();
    score_count_kernel<<<SCORE_BLOCKS + (EE + 255) / 256, 256>>>(x, pool_p, ei, ew);
    scan_kernel<<<1, 1024>>>();
    thresh_kernel<<<1, 256>>>();
    collect_kernel<<<(NN + 255) / 256, 256>>>();
    final_topk_kernel<<<1, 32>>>();
    gru_kernel<<<64, 64>>>(x, pool_p, init_W, Wih, Whh, bih, bhh);
    fill_kernel<<<(EE + 255) / 256, 256>>>(ei, ew);
    xw_kernel<<<(NN + 15) / 16, 256>>>(x);
    gather_out_kernel<<<(NN + 7) / 8, 256>>>(linW, linb, out);
}